// round 14
// baseline (speedup 1.0000x reference)
#include <cuda_runtime.h>
#include <cuda_fp16.h>
#include <cstdint>

// Problem constants (fixed by the dataset)
#define NN   100000       // nodes
#define NE   1600000      // edges (excluding self loops)
#define FD   128          // feature / hidden dim
#define NC   64           // classes
#define NB_SCAN 98        // ceil(NN / 1024)
#define NTILES 782        // ceil(NN / 128)
#define GEMM_GRID 296     // 2 CTAs/SM * 148 SMs

// ---------------- scratch (device globals; no allocation allowed) ----------
__device__ __half g_xh[NN * FD];     // x converted to fp16 (GEMM-1 input)
__device__ __half g_h1[NN * FD];     // layer-1 GEMM output (gather source 1)
__device__ __half g_h2[NN * FD];     // layer-2 fused output (gather source 2)
__device__ float  g_dinv[NN];
__device__ int    g_deg[NN];         // in-degree (without self loop)
__device__ int    g_rowstart[NN];    // AFTER k_fill: END offset of each row
__device__ int2   g_pair[NE];        // (src, norm-bits) per edge, grouped by dst
__device__ int    g_status[NB_SCAN]; // lookback scan status (memset to 0)

__device__ __forceinline__ uint32_t pack_h2(float x, float y)
{
    __half2 h = __floats2half2_rn(x, y);
    return *reinterpret_cast<uint32_t*>(&h);
}

// ---------------- preprocessing kernels ------------------------------------

// Fused: degree count (threads < NE) + x -> fp16 conversion (all 3.2M threads).
__global__ void k_count_cvt(const int* __restrict__ ei,
                            const float4* __restrict__ x,
                            uint2* __restrict__ xh)
{
    int i = blockIdx.x * blockDim.x + threadIdx.x;
    if (i < NE) {
        int d = ei[NE + i];
        atomicAdd(&g_deg[d], 1);
    }
    float4 v = __ldg(&x[i]);
    uint2 p;
    p.x = pack_h2(v.x, v.y);
    p.y = pack_h2(v.z, v.w);
    xh[i] = p;
}

// Single-pass scan over g_deg -> g_rowstart (exclusive), plus dinv.
__global__ void __launch_bounds__(1024) k_scan()
{
    __shared__ int s[1024];
    __shared__ int sh_prefix;
    int t = threadIdx.x;
    int i = blockIdx.x * 1024 + t;
    int v = (i < NN) ? g_deg[i] : 0;
    s[t] = v;
    __syncthreads();
    #pragma unroll
    for (int off = 1; off < 1024; off <<= 1) {
        int add = (t >= off) ? s[t - off] : 0;
        __syncthreads();
        s[t] += add;
        __syncthreads();
    }
    if (t == 1023) {
        int total = s[t];
        __threadfence();
        atomicExch(&g_status[blockIdx.x], total | 0x40000000);
    }
    if (t == 0) {
        int p = 0;
        for (int j = 0; j < (int)blockIdx.x; j++) {
            int st;
            do { st = atomicAdd(&g_status[j], 0); } while (!(st & 0x40000000));
            p += st & 0x3FFFFFFF;
        }
        sh_prefix = p;
    }
    __syncthreads();
    if (i < NN) {
        g_rowstart[i] = s[t] - v + sh_prefix;
        g_dinv[i] = rsqrtf((float)v + 1.0f);    // +1 = self loop
    }
}

// Bumps g_rowstart in place: after this kernel rowstart[d] == END of row d.
// Consumers compute beg = rowstart[d] - deg[d].
__global__ void k_fill(const int* __restrict__ ei)
{
    int e = blockIdx.x * blockDim.x + threadIdx.x;
    if (e < NE) {
        int s = ei[e];
        int d = ei[NE + e];
        int p = atomicAdd(&g_rowstart[d], 1);
        float nm = __ldg(&g_dinv[s]) * __ldg(&g_dinv[d]);
        g_pair[p] = make_int2(s, __float_as_int(nm));
    }
}

// ---------------- fp16 MMA helper ------------------------------------------
__device__ __forceinline__ void mma_f16(
    float& d0, float& d1, float& d2, float& d3,
    uint32_t a0, uint32_t a1, uint32_t a2, uint32_t a3,
    uint32_t b0, uint32_t b1)
{
    asm volatile(
        "mma.sync.aligned.m16n8k16.row.col.f32.f16.f16.f32 "
        "{%0,%1,%2,%3}, {%4,%5,%6,%7}, {%8,%9}, {%0,%1,%2,%3};"
        : "+f"(d0), "+f"(d1), "+f"(d2), "+f"(d3)
        : "r"(a0), "r"(a1), "r"(a2), "r"(a3), "r"(b0), "r"(b1));
}

// ------- warp-level aggregation of ONE node into 8 fp32 dims/lane ----------
// LDG.128 parity gather, tail-free, f32x2 accumulation. Returns via acc[8]:
// lane covers dims [8*(lane&15) .. 8*(lane&15)+7] (after the parity merge).
__device__ __forceinline__ void agg_node(
    const uint4* __restrict__ hp, int node, int lane,
    const float* __restrict__ bias_l, float* r /*8 outputs, relu'd*/)
{
    const int half = lane >> 4;
    const int sub  = lane & 15;
    const int end = g_rowstart[node];
    const int cnt = g_deg[node];
    const int beg = end - cnt;

    unsigned long long acc64[4];
    #pragma unroll
    for (int d = 0; d < 4; d++) acc64[d] = 0ull;

    for (int t0 = 0; t0 < cnt; t0 += 32) {
        int2 pr = make_int2(0, 0);
        if (t0 + lane < cnt) pr = __ldg(&g_pair[beg + t0 + lane]);
        int m = min(32, cnt - t0);
        #pragma unroll
        for (int g = 0; g < 2; g++) {
            if (g * 16 >= m) break;
            uint4 u[8];
            #pragma unroll
            for (int q = 0; q < 8; q++) {
                int src = __shfl_sync(0xFFFFFFFFu, pr.x, g * 16 + 2 * q + half);
                u[q] = __ldg(&hp[(size_t)src * 16 + sub]);
            }
            #pragma unroll
            for (int q = 0; q < 8; q++) {
                float nf = __int_as_float(
                    __shfl_sync(0xFFFFFFFFu, pr.y, g * 16 + 2 * q + half));
                unsigned long long n2;
                asm("mov.b64 %0, {%1, %1};" : "=l"(n2) : "f"(nf));
                float2 f0 = __half22float2(*reinterpret_cast<__half2*>(&u[q].x));
                float2 f1 = __half22float2(*reinterpret_cast<__half2*>(&u[q].y));
                float2 f2 = __half22float2(*reinterpret_cast<__half2*>(&u[q].z));
                float2 f3 = __half22float2(*reinterpret_cast<__half2*>(&u[q].w));
                unsigned long long v0, v1, v2, v3;
                asm("mov.b64 %0, {%1, %2};" : "=l"(v0) : "f"(f0.x), "f"(f0.y));
                asm("mov.b64 %0, {%1, %2};" : "=l"(v1) : "f"(f1.x), "f"(f1.y));
                asm("mov.b64 %0, {%1, %2};" : "=l"(v2) : "f"(f2.x), "f"(f2.y));
                asm("mov.b64 %0, {%1, %2};" : "=l"(v3) : "f"(f3.x), "f"(f3.y));
                asm("fma.rn.f32x2 %0, %1, %2, %0;" : "+l"(acc64[0]) : "l"(v0), "l"(n2));
                asm("fma.rn.f32x2 %0, %1, %2, %0;" : "+l"(acc64[1]) : "l"(v1), "l"(n2));
                asm("fma.rn.f32x2 %0, %1, %2, %0;" : "+l"(acc64[2]) : "l"(v2), "l"(n2));
                asm("fma.rn.f32x2 %0, %1, %2, %0;" : "+l"(acc64[3]) : "l"(v3), "l"(n2));
            }
        }
    }

    float acc[8];
    #pragma unroll
    for (int d = 0; d < 4; d++) {
        asm("mov.b64 {%0, %1}, %2;"
            : "=f"(acc[2 * d]), "=f"(acc[2 * d + 1]) : "l"(acc64[d]));
    }
    #pragma unroll
    for (int d = 0; d < 8; d++)
        acc[d] += __shfl_xor_sync(0xFFFFFFFFu, acc[d], 16);

    float dinv_d = g_dinv[node];
    float c = dinv_d * dinv_d;
    uint4 us = __ldg(&hp[(size_t)node * 16 + sub]);
    float2 s0 = __half22float2(*reinterpret_cast<__half2*>(&us.x));
    float2 s1 = __half22float2(*reinterpret_cast<__half2*>(&us.y));
    float2 s2 = __half22float2(*reinterpret_cast<__half2*>(&us.z));
    float2 s3 = __half22float2(*reinterpret_cast<__half2*>(&us.w));
    const float4* b4 = reinterpret_cast<const float4*>(bias_l);
    float4 ba = __ldg(&b4[sub * 2]);
    float4 bb = __ldg(&b4[sub * 2 + 1]);
    r[0] = fmaxf(acc[0] + c * s0.x + ba.x, 0.f);
    r[1] = fmaxf(acc[1] + c * s0.y + ba.y, 0.f);
    r[2] = fmaxf(acc[2] + c * s1.x + ba.z, 0.f);
    r[3] = fmaxf(acc[3] + c * s1.y + ba.w, 0.f);
    r[4] = fmaxf(acc[4] + c * s2.x + bb.x, 0.f);
    r[5] = fmaxf(acc[5] + c * s2.y + bb.y, 0.f);
    r[6] = fmaxf(acc[6] + c * s3.x + bb.z, 0.f);
    r[7] = fmaxf(acc[7] + c * s3.y + bb.w, 0.f);
}

// ---------------- GEMM: C[NN, OUT] = A[NN,128] @ W[OUT,128]^T (+bias) ------
// Persistent multi-tile fp16 MMA GEMM with cp.async double-buffered A tiles.
// (layer 1 only: A = xh, dense)
template <int OUT, bool HOUT>
__global__ void __launch_bounds__(256, 2) k_gemm(
    const __half* __restrict__ A, const float* __restrict__ W,
    const float* __restrict__ bias, void* __restrict__ Cv)
{
    constexpr int NA = OUT / 16;
    constexpr int XWORDS = 128 * 68;
    extern __shared__ uint32_t sm[];
    uint32_t* Xstage[2] = { sm, sm + XWORDS };
    uint32_t* Ws = sm + 2 * XWORDS;
    const int tid  = threadIdx.x;
    const int warp = tid >> 5;
    const int lane = tid & 31;

    const int m_off = (warp >> 1) * 32;
    const int n_off = (warp & 1) * (OUT / 2);
    const int gid = lane >> 2;
    const int tig = lane & 3;

    auto fill_async = [&](uint32_t* Xs, int t) {
        int row0 = t * 128;
        #pragma unroll
        for (int i = 0; i < 8; i++) {
            int idx = tid + i * 256;
            int r = idx >> 4, c8 = idx & 15;
            uint32_t dst = (uint32_t)__cvta_generic_to_shared(&Xs[r * 68 + c8 * 4]);
            const void* src = (const char*)A + ((size_t)(row0 + r) * 128 + c8 * 8) * 2;
            int sz = (row0 + r < NN) ? 16 : 0;
            asm volatile("cp.async.cg.shared.global [%0], [%1], 16, %2;"
                         :: "r"(dst), "l"(src), "r"(sz));
        }
        asm volatile("cp.async.commit_group;");
    };

    int tile = blockIdx.x;
    if (tile < NTILES) fill_async(Xstage[0], tile);

    for (int idx = tid; idx < OUT * 32; idx += 256) {
        int j = idx >> 5, c4 = idx & 31;
        float4 v = reinterpret_cast<const float4*>(W)[idx];
        uint2 p;
        p.x = pack_h2(v.x, v.y);
        p.y = pack_h2(v.z, v.w);
        *reinterpret_cast<uint2*>(&Ws[j * 68 + c4 * 2]) = p;
    }

    int stage = 0;
    for (; tile < NTILES; tile += GEMM_GRID) {
        int next = tile + GEMM_GRID;
        if (next < NTILES) {
            fill_async(Xstage[stage ^ 1], next);
            asm volatile("cp.async.wait_group 1;");
        } else {
            asm volatile("cp.async.wait_group 0;");
        }
        __syncthreads();
        const uint32_t* Xs = Xstage[stage];
        const int row0 = tile * 128;

        float acc[2][NA][4];
        #pragma unroll
        for (int ma = 0; ma < 2; ma++)
            #pragma unroll
            for (int na = 0; na < NA; na++)
                #pragma unroll
                for (int c = 0; c < 4; c++) acc[ma][na][c] = 0.f;

        #pragma unroll
        for (int ks = 0; ks < 8; ks++) {
            uint32_t a[2][4];
            #pragma unroll
            for (int ma = 0; ma < 2; ma++) {
                int row = m_off + ma * 16 + gid;
                a[ma][0] = Xs[row * 68 + ks * 8 + tig];
                a[ma][1] = Xs[(row + 8) * 68 + ks * 8 + tig];
                a[ma][2] = Xs[row * 68 + ks * 8 + tig + 4];
                a[ma][3] = Xs[(row + 8) * 68 + ks * 8 + tig + 4];
            }
            #pragma unroll
            for (int na = 0; na < NA; na++) {
                int n = n_off + na * 8 + gid;
                uint32_t b0 = Ws[n * 68 + ks * 8 + tig];
                uint32_t b1 = Ws[n * 68 + ks * 8 + tig + 4];
                #pragma unroll
                for (int ma = 0; ma < 2; ma++) {
                    float* d = acc[ma][na];
                    mma_f16(d[0], d[1], d[2], d[3],
                            a[ma][0], a[ma][1], a[ma][2], a[ma][3], b0, b1);
                }
            }
        }

        #pragma unroll
        for (int ma = 0; ma < 2; ma++) {
            #pragma unroll
            for (int na = 0; na < NA; na++) {
                int col = n_off + na * 8 + 2 * tig;
                float bx = 0.f, by = 0.f;
                if (bias) { bx = __ldg(&bias[col]); by = __ldg(&bias[col + 1]); }
                int r0 = row0 + m_off + ma * 16 + gid;
                int r1 = r0 + 8;
                if (HOUT) {
                    __half* C = (__half*)Cv;
                    if (r0 < NN)
                        *reinterpret_cast<__half2*>(&C[(size_t)r0 * OUT + col]) =
                            __floats2half2_rn(acc[ma][na][0] + bx, acc[ma][na][1] + by);
                    if (r1 < NN)
                        *reinterpret_cast<__half2*>(&C[(size_t)r1 * OUT + col]) =
                            __floats2half2_rn(acc[ma][na][2] + bx, acc[ma][na][3] + by);
                } else {
                    float* C = (float*)Cv;
                    if (r0 < NN)
                        *reinterpret_cast<float2*>(&C[(size_t)r0 * OUT + col]) =
                            make_float2(acc[ma][na][0] + bx, acc[ma][na][1] + by);
                    if (r1 < NN)
                        *reinterpret_cast<float2*>(&C[(size_t)r1 * OUT + col]) =
                            make_float2(acc[ma][na][2] + bx, acc[ma][na][3] + by);
                }
            }
        }
        __syncthreads();
        stage ^= 1;
    }
}

// ------- FUSED agg + GEMM: C = relu(Agg(h) + b_l) @ W^T (+bias_o) ----------
// Per 128-row tile: 8 warps aggregate 16 nodes each directly into the smem
// A-tile (fp16), then MMA. 2 CTAs/SM overlap gather and MMA phases.
template <int OUT, bool HOUT>
__global__ void __launch_bounds__(256, 2) k_agg_gemm(
    const __half* __restrict__ h, const float* __restrict__ bias_l,
    const float* __restrict__ W, const float* __restrict__ bias_o,
    void* __restrict__ Cv)
{
    constexpr int NA = OUT / 16;
    extern __shared__ uint32_t sm[];
    uint32_t* Xs = sm;                    // [128][68] fp16 A tile
    uint32_t* Ws = sm + 128 * 68;         // [OUT][68]
    const int tid  = threadIdx.x;
    const int warp = tid >> 5;
    const int lane = tid & 31;
    const int sub  = lane & 15;

    const int m_off = (warp >> 1) * 32;
    const int n_off = (warp & 1) * (OUT / 2);
    const int gid = lane >> 2;
    const int tig = lane & 3;

    // W tile load + convert (once per CTA)
    for (int idx = tid; idx < OUT * 32; idx += 256) {
        int j = idx >> 5, c4 = idx & 31;
        float4 v = reinterpret_cast<const float4*>(W)[idx];
        uint2 p;
        p.x = pack_h2(v.x, v.y);
        p.y = pack_h2(v.z, v.w);
        *reinterpret_cast<uint2*>(&Ws[j * 68 + c4 * 2]) = p;
    }

    const uint4* hp = reinterpret_cast<const uint4*>(h);

    for (int tile = blockIdx.x; tile < NTILES; tile += GEMM_GRID) {
        const int row0 = tile * 128;

        // ---- aggregation phase: warp w -> local rows w*16 .. w*16+15 ----
        for (int rr = 0; rr < 16; rr++) {
            int lr = warp * 16 + rr;
            int node = row0 + lr;
            uint4 o = make_uint4(0u, 0u, 0u, 0u);
            if (node < NN) {
                float r[8];
                agg_node(hp, node, lane, bias_l, r);
                o.x = pack_h2(r[0], r[1]);
                o.y = pack_h2(r[2], r[3]);
                o.z = pack_h2(r[4], r[5]);
                o.w = pack_h2(r[6], r[7]);
            }
            if (lane < 16)
                *reinterpret_cast<uint4*>(&Xs[lr * 68 + sub * 4]) = o;
        }
        __syncthreads();

        // ---- MMA phase ----
        float acc[2][NA][4];
        #pragma unroll
        for (int ma = 0; ma < 2; ma++)
            #pragma unroll
            for (int na = 0; na < NA; na++)
                #pragma unroll
                for (int c = 0; c < 4; c++) acc[ma][na][c] = 0.f;

        #pragma unroll
        for (int ks = 0; ks < 8; ks++) {
            uint32_t a[2][4];
            #pragma unroll
            for (int ma = 0; ma < 2; ma++) {
                int row = m_off + ma * 16 + gid;
                a[ma][0] = Xs[row * 68 + ks * 8 + tig];
                a[ma][1] = Xs[(row + 8) * 68 + ks * 8 + tig];
                a[ma][2] = Xs[row * 68 + ks * 8 + tig + 4];
                a[ma][3] = Xs[(row + 8) * 68 + ks * 8 + tig + 4];
            }
            #pragma unroll
            for (int na = 0; na < NA; na++) {
                int n = n_off + na * 8 + gid;
                uint32_t b0 = Ws[n * 68 + ks * 8 + tig];
                uint32_t b1 = Ws[n * 68 + ks * 8 + tig + 4];
                #pragma unroll
                for (int ma = 0; ma < 2; ma++) {
                    float* d = acc[ma][na];
                    mma_f16(d[0], d[1], d[2], d[3],
                            a[ma][0], a[ma][1], a[ma][2], a[ma][3], b0, b1);
                }
            }
        }

        // ---- epilogue ----
        #pragma unroll
        for (int ma = 0; ma < 2; ma++) {
            #pragma unroll
            for (int na = 0; na < NA; na++) {
                int col = n_off + na * 8 + 2 * tig;
                float bx = 0.f, by = 0.f;
                if (bias_o) { bx = __ldg(&bias_o[col]); by = __ldg(&bias_o[col + 1]); }
                int r0 = row0 + m_off + ma * 16 + gid;
                int r1 = r0 + 8;
                if (HOUT) {
                    __half* C = (__half*)Cv;
                    if (r0 < NN)
                        *reinterpret_cast<__half2*>(&C[(size_t)r0 * OUT + col]) =
                            __floats2half2_rn(acc[ma][na][0] + bx, acc[ma][na][1] + by);
                    if (r1 < NN)
                        *reinterpret_cast<__half2*>(&C[(size_t)r1 * OUT + col]) =
                            __floats2half2_rn(acc[ma][na][2] + bx, acc[ma][na][3] + by);
                } else {
                    float* C = (float*)Cv;
                    if (r0 < NN)
                        *reinterpret_cast<float2*>(&C[(size_t)r0 * OUT + col]) =
                            make_float2(acc[ma][na][0] + bx, acc[ma][na][1] + by);
                    if (r1 < NN)
                        *reinterpret_cast<float2*>(&C[(size_t)r1 * OUT + col]) =
                            make_float2(acc[ma][na][2] + bx, acc[ma][na][3] + by);
                }
            }
        }
        __syncthreads();   // protect Xs before next tile's agg writes
    }
}

// ---------------- launcher --------------------------------------------------
extern "C" void kernel_launch(void* const* d_in, const int* in_sizes, int n_in,
                              void* d_out, int out_size)
{
    (void)in_sizes; (void)n_in; (void)out_size;
    const float* x  = (const float*)d_in[0];
    const int*   ei = (const int*)d_in[1];          // int32 (JAX x64 disabled)
    const float* W1 = (const float*)d_in[2];
    const float* b1 = (const float*)d_in[3];
    const float* W2 = (const float*)d_in[4];
    const float* b2 = (const float*)d_in[5];
    const float* Wl = (const float*)d_in[6];
    const float* bl = (const float*)d_in[7];
    float* out = (float*)d_out;

    void *pxh, *ph1, *ph2, *pdeg, *pst;
    cudaGetSymbolAddress(&pxh, g_xh);
    cudaGetSymbolAddress(&ph1, g_h1);
    cudaGetSymbolAddress(&ph2, g_h2);
    cudaGetSymbolAddress(&pdeg, g_deg);
    cudaGetSymbolAddress(&pst,  g_status);
    __half* xh = (__half*)pxh;
    __half* h1 = (__half*)ph1;
    __half* h2 = (__half*)ph2;

    const int SMEM_G128 = (2 * 128 * 68 + 128 * 68) * 4;   // 104448 B (k_gemm)
    const int SMEM_F128 = (128 * 68 + 128 * 68) * 4;       // 69632 B (fused 128)
    const int SMEM_F64  = (128 * 68 + 64 * 68) * 4;        // 52224 B (fused 64)
    cudaFuncSetAttribute((const void*)k_gemm<128, true>,
                         cudaFuncAttributeMaxDynamicSharedMemorySize, SMEM_G128);
    cudaFuncSetAttribute((const void*)k_agg_gemm<128, true>,
                         cudaFuncAttributeMaxDynamicSharedMemorySize, SMEM_F128);
    cudaFuncSetAttribute((const void*)k_agg_gemm<64, false>,
                         cudaFuncAttributeMaxDynamicSharedMemorySize, SMEM_F64);

    const int TB = 256;
    const int GB_E = (NE + TB - 1) / TB;           // 6250
    const int GB_C = (NN * 32 + TB - 1) / TB;      // 12500

    // --- zero-init via memset nodes ---
    cudaMemsetAsync(pdeg, 0, NN * sizeof(int));
    cudaMemsetAsync(pst,  0, NB_SCAN * sizeof(int));

    // --- preprocessing ---
    k_count_cvt<<<GB_C, TB>>>(ei, (const float4*)x, (uint2*)xh);
    k_scan<<<NB_SCAN, 1024>>>();
    k_fill<<<GB_E, TB>>>(ei);

    // --- layer 1 GEMM (profile slot 4) ---
    k_gemm<128, true><<<GEMM_GRID, TB, SMEM_G128>>>(xh, W1, nullptr, h1);

    // --- fused agg1 + GEMM2 ---
    k_agg_gemm<128, true><<<GEMM_GRID, TB, SMEM_F128>>>(h1, b1, W2, nullptr, h2);

    // --- fused agg2 + readout GEMM ---
    k_agg_gemm<64, false><<<GEMM_GRID, TB, SMEM_F64>>>(h2, b2, Wl, bl, out);
}

// round 15
// speedup vs baseline: 1.2126x; 1.2126x over previous
#include <cuda_runtime.h>
#include <cuda_fp16.h>
#include <cstdint>

// Problem constants (fixed by the dataset)
#define NN   100000       // nodes
#define NE   1600000      // edges (excluding self loops)
#define FD   128          // feature / hidden dim
#define NC   64           // classes
#define NB_SCAN 98        // ceil(NN / 1024)
#define NTILES 782        // ceil(NN / 128)
#define GEMM_GRID 296     // 2 CTAs/SM * 148 SMs

// ---------------- scratch (device globals; no allocation allowed) ----------
__device__ __half g_xh[NN * FD];     // x converted to fp16 (GEMM-1 input)
__device__ __half g_bufh[NN * FD];   // GEMM output h (fp16, gather operand)
__device__ __half g_bufact[NN * FD]; // agg+relu output (fp16, GEMM input)
__device__ float  g_dinv[NN];
__device__ int    g_deg[NN];         // in-degree (without self loop)
__device__ int    g_rowstart[NN];    // AFTER k_fill: END offset of each row
__device__ int2   g_pair[NE];        // (src, norm-bits) per edge, grouped by dst
__device__ int    g_status[NB_SCAN]; // lookback scan status (memset to 0)

__device__ __forceinline__ uint32_t pack_h2(float x, float y)
{
    __half2 h = __floats2half2_rn(x, y);
    return *reinterpret_cast<uint32_t*>(&h);
}

// ---------------- preprocessing kernels ------------------------------------

// Fused: degree count (threads < NE) + x -> fp16 conversion (all 3.2M threads).
__global__ void k_count_cvt(const int* __restrict__ ei,
                            const float4* __restrict__ x,
                            uint2* __restrict__ xh)
{
    int i = blockIdx.x * blockDim.x + threadIdx.x;
    if (i < NE) {
        int d = ei[NE + i];
        atomicAdd(&g_deg[d], 1);
    }
    float4 v = __ldg(&x[i]);
    uint2 p;
    p.x = pack_h2(v.x, v.y);
    p.y = pack_h2(v.z, v.w);
    xh[i] = p;
}

// Single-pass scan over g_deg -> g_rowstart (exclusive), plus dinv.
__global__ void __launch_bounds__(1024) k_scan()
{
    __shared__ int s[1024];
    __shared__ int sh_prefix;
    int t = threadIdx.x;
    int i = blockIdx.x * 1024 + t;
    int v = (i < NN) ? g_deg[i] : 0;
    s[t] = v;
    __syncthreads();
    #pragma unroll
    for (int off = 1; off < 1024; off <<= 1) {
        int add = (t >= off) ? s[t - off] : 0;
        __syncthreads();
        s[t] += add;
        __syncthreads();
    }
    if (t == 1023) {
        int total = s[t];
        __threadfence();
        atomicExch(&g_status[blockIdx.x], total | 0x40000000);
    }
    if (t == 0) {
        int p = 0;
        for (int j = 0; j < (int)blockIdx.x; j++) {
            int st;
            do { st = atomicAdd(&g_status[j], 0); } while (!(st & 0x40000000));
            p += st & 0x3FFFFFFF;
        }
        sh_prefix = p;
    }
    __syncthreads();
    if (i < NN) {
        g_rowstart[i] = s[t] - v + sh_prefix;
        g_dinv[i] = rsqrtf((float)v + 1.0f);    // +1 = self loop
    }
}

// Bumps g_rowstart in place: after this kernel rowstart[d] == END of row d.
// Consumers compute beg = rowstart[d] - deg[d].
__global__ void k_fill(const int* __restrict__ ei)
{
    int e = blockIdx.x * blockDim.x + threadIdx.x;
    if (e < NE) {
        int s = ei[e];
        int d = ei[NE + e];
        int p = atomicAdd(&g_rowstart[d], 1);
        float nm = __ldg(&g_dinv[s]) * __ldg(&g_dinv[d]);
        g_pair[p] = make_int2(s, __float_as_int(nm));
    }
}

// ---------------- fp16 MMA helper ------------------------------------------
__device__ __forceinline__ void mma_f16(
    float& d0, float& d1, float& d2, float& d3,
    uint32_t a0, uint32_t a1, uint32_t a2, uint32_t a3,
    uint32_t b0, uint32_t b1)
{
    asm volatile(
        "mma.sync.aligned.m16n8k16.row.col.f32.f16.f16.f32 "
        "{%0,%1,%2,%3}, {%4,%5,%6,%7}, {%8,%9}, {%0,%1,%2,%3};"
        : "+f"(d0), "+f"(d1), "+f"(d2), "+f"(d3)
        : "r"(a0), "r"(a1), "r"(a2), "r"(a3), "r"(b0), "r"(b1));
}

// ---------------- GEMM: C[NN, OUT] = A[NN,128] @ W[OUT,128]^T (+bias) ------
// Persistent multi-tile fp16 MMA GEMM with cp.async double-buffered A tiles.
template <int OUT, bool HOUT>
__global__ void __launch_bounds__(256, 2) k_gemm(
    const __half* __restrict__ A, const float* __restrict__ W,
    const float* __restrict__ bias, void* __restrict__ Cv)
{
    constexpr int NA = OUT / 16;
    constexpr int XWORDS = 128 * 68;
    extern __shared__ uint32_t sm[];
    uint32_t* Xstage[2] = { sm, sm + XWORDS };
    uint32_t* Ws = sm + 2 * XWORDS;
    const int tid  = threadIdx.x;
    const int warp = tid >> 5;
    const int lane = tid & 31;

    const int m_off = (warp >> 1) * 32;
    const int n_off = (warp & 1) * (OUT / 2);
    const int gid = lane >> 2;
    const int tig = lane & 3;

    auto fill_async = [&](uint32_t* Xs, int t) {
        int row0 = t * 128;
        #pragma unroll
        for (int i = 0; i < 8; i++) {
            int idx = tid + i * 256;
            int r = idx >> 4, c8 = idx & 15;
            uint32_t dst = (uint32_t)__cvta_generic_to_shared(&Xs[r * 68 + c8 * 4]);
            const void* src = (const char*)A + ((size_t)(row0 + r) * 128 + c8 * 8) * 2;
            int sz = (row0 + r < NN) ? 16 : 0;
            asm volatile("cp.async.cg.shared.global [%0], [%1], 16, %2;"
                         :: "r"(dst), "l"(src), "r"(sz));
        }
        asm volatile("cp.async.commit_group;");
    };

    int tile = blockIdx.x;
    if (tile < NTILES) fill_async(Xstage[0], tile);

    for (int idx = tid; idx < OUT * 32; idx += 256) {
        int j = idx >> 5, c4 = idx & 31;
        float4 v = reinterpret_cast<const float4*>(W)[idx];
        uint2 p;
        p.x = pack_h2(v.x, v.y);
        p.y = pack_h2(v.z, v.w);
        *reinterpret_cast<uint2*>(&Ws[j * 68 + c4 * 2]) = p;
    }

    int stage = 0;
    for (; tile < NTILES; tile += GEMM_GRID) {
        int next = tile + GEMM_GRID;
        if (next < NTILES) {
            fill_async(Xstage[stage ^ 1], next);
            asm volatile("cp.async.wait_group 1;");
        } else {
            asm volatile("cp.async.wait_group 0;");
        }
        __syncthreads();
        const uint32_t* Xs = Xstage[stage];
        const int row0 = tile * 128;

        float acc[2][NA][4];
        #pragma unroll
        for (int ma = 0; ma < 2; ma++)
            #pragma unroll
            for (int na = 0; na < NA; na++)
                #pragma unroll
                for (int c = 0; c < 4; c++) acc[ma][na][c] = 0.f;

        #pragma unroll
        for (int ks = 0; ks < 8; ks++) {
            uint32_t a[2][4];
            #pragma unroll
            for (int ma = 0; ma < 2; ma++) {
                int row = m_off + ma * 16 + gid;
                a[ma][0] = Xs[row * 68 + ks * 8 + tig];
                a[ma][1] = Xs[(row + 8) * 68 + ks * 8 + tig];
                a[ma][2] = Xs[row * 68 + ks * 8 + tig + 4];
                a[ma][3] = Xs[(row + 8) * 68 + ks * 8 + tig + 4];
            }
            #pragma unroll
            for (int na = 0; na < NA; na++) {
                int n = n_off + na * 8 + gid;
                uint32_t b0 = Ws[n * 68 + ks * 8 + tig];
                uint32_t b1 = Ws[n * 68 + ks * 8 + tig + 4];
                #pragma unroll
                for (int ma = 0; ma < 2; ma++) {
                    float* d = acc[ma][na];
                    mma_f16(d[0], d[1], d[2], d[3],
                            a[ma][0], a[ma][1], a[ma][2], a[ma][3], b0, b1);
                }
            }
        }

        #pragma unroll
        for (int ma = 0; ma < 2; ma++) {
            #pragma unroll
            for (int na = 0; na < NA; na++) {
                int col = n_off + na * 8 + 2 * tig;
                float bx = 0.f, by = 0.f;
                if (bias) { bx = __ldg(&bias[col]); by = __ldg(&bias[col + 1]); }
                int r0 = row0 + m_off + ma * 16 + gid;
                int r1 = r0 + 8;
                if (HOUT) {
                    __half* C = (__half*)Cv;
                    if (r0 < NN)
                        *reinterpret_cast<__half2*>(&C[(size_t)r0 * OUT + col]) =
                            __floats2half2_rn(acc[ma][na][0] + bx, acc[ma][na][1] + by);
                    if (r1 < NN)
                        *reinterpret_cast<__half2*>(&C[(size_t)r1 * OUT + col]) =
                            __floats2half2_rn(acc[ma][na][2] + bx, acc[ma][na][3] + by);
                } else {
                    float* C = (float*)Cv;
                    if (r0 < NN)
                        *reinterpret_cast<float2*>(&C[(size_t)r0 * OUT + col]) =
                            make_float2(acc[ma][na][0] + bx, acc[ma][na][1] + by);
                    if (r1 < NN)
                        *reinterpret_cast<float2*>(&C[(size_t)r1 * OUT + col]) =
                            make_float2(acc[ma][na][2] + bx, acc[ma][na][3] + by);
                }
            }
        }
        __syncthreads();
        stage ^= 1;
    }
}

// -------- aggregation + self-loop + bias + ReLU: HALF-WARP per node --------
// Lanes 0-15 own node 2w, lanes 16-31 own node 2w+1. Each lane covers dims
// [8*(lane&15) .. +7] (16 lanes x 16B = full 256B row). Pairs loaded per-half,
// shfl'd with half-masks (halves fully independent, divergent degrees OK).
// 8 LDG.128 in flight per half (16 per warp); no cross-lane reduction needed.
__global__ void __launch_bounds__(256, 4) k_agg_relu(
    const __half* __restrict__ h,
    const float* __restrict__ bias,
    __half* __restrict__ out)
{
    const int lane = threadIdx.x & 31;
    const int halfid = lane >> 4;
    const int sub  = lane & 15;
    int node = ((blockIdx.x * blockDim.x + threadIdx.x) >> 5) * 2 + halfid;
    if (node >= NN) return;
    const unsigned mask = 0xFFFFu << (halfid * 16);

    const int end = g_rowstart[node];
    const int cnt = g_deg[node];
    const int beg = end - cnt;
    const uint4* hp = reinterpret_cast<const uint4*>(h);     // 16 uint4 / row

    unsigned long long acc64[4];
    #pragma unroll
    for (int d = 0; d < 4; d++) acc64[d] = 0ull;

    for (int t0 = 0; t0 < cnt; t0 += 16) {
        int2 pr = make_int2(0, 0);                 // src=0, norm=0 (inert)
        if (t0 + sub < cnt) pr = __ldg(&g_pair[beg + t0 + sub]);
        int m = min(16, cnt - t0);
        #pragma unroll
        for (int g = 0; g < 2; g++) {
            if (g * 8 >= m) break;
            uint4 u[8];
            #pragma unroll
            for (int q = 0; q < 8; q++) {
                int src = __shfl_sync(mask, pr.x, (halfid << 4) + g * 8 + q);
                u[q] = __ldg(&hp[(size_t)src * 16 + sub]);
            }
            #pragma unroll
            for (int q = 0; q < 8; q++) {
                float nf = __int_as_float(
                    __shfl_sync(mask, pr.y, (halfid << 4) + g * 8 + q));
                unsigned long long n2;
                asm("mov.b64 %0, {%1, %1};" : "=l"(n2) : "f"(nf));
                float2 f0 = __half22float2(*reinterpret_cast<__half2*>(&u[q].x));
                float2 f1 = __half22float2(*reinterpret_cast<__half2*>(&u[q].y));
                float2 f2 = __half22float2(*reinterpret_cast<__half2*>(&u[q].z));
                float2 f3 = __half22float2(*reinterpret_cast<__half2*>(&u[q].w));
                unsigned long long v0, v1, v2, v3;
                asm("mov.b64 %0, {%1, %2};" : "=l"(v0) : "f"(f0.x), "f"(f0.y));
                asm("mov.b64 %0, {%1, %2};" : "=l"(v1) : "f"(f1.x), "f"(f1.y));
                asm("mov.b64 %0, {%1, %2};" : "=l"(v2) : "f"(f2.x), "f"(f2.y));
                asm("mov.b64 %0, {%1, %2};" : "=l"(v3) : "f"(f3.x), "f"(f3.y));
                asm("fma.rn.f32x2 %0, %1, %2, %0;" : "+l"(acc64[0]) : "l"(v0), "l"(n2));
                asm("fma.rn.f32x2 %0, %1, %2, %0;" : "+l"(acc64[1]) : "l"(v1), "l"(n2));
                asm("fma.rn.f32x2 %0, %1, %2, %0;" : "+l"(acc64[2]) : "l"(v2), "l"(n2));
                asm("fma.rn.f32x2 %0, %1, %2, %0;" : "+l"(acc64[3]) : "l"(v3), "l"(n2));
            }
        }
    }

    float acc[8];
    #pragma unroll
    for (int d = 0; d < 4; d++) {
        asm("mov.b64 {%0, %1}, %2;"
            : "=f"(acc[2 * d]), "=f"(acc[2 * d + 1]) : "l"(acc64[d]));
    }

    // self-loop + bias + ReLU; every lane writes its 16B chunk of its node
    float dinv_d = g_dinv[node];
    float c = dinv_d * dinv_d;
    uint4 us = __ldg(&hp[(size_t)node * 16 + sub]);
    float2 s0 = __half22float2(*reinterpret_cast<__half2*>(&us.x));
    float2 s1 = __half22float2(*reinterpret_cast<__half2*>(&us.y));
    float2 s2 = __half22float2(*reinterpret_cast<__half2*>(&us.z));
    float2 s3 = __half22float2(*reinterpret_cast<__half2*>(&us.w));
    const float4* b4 = reinterpret_cast<const float4*>(bias);
    float4 ba = __ldg(&b4[sub * 2]);
    float4 bb = __ldg(&b4[sub * 2 + 1]);
    float r0 = fmaxf(acc[0] + c * s0.x + ba.x, 0.f);
    float r1 = fmaxf(acc[1] + c * s0.y + ba.y, 0.f);
    float r2 = fmaxf(acc[2] + c * s1.x + ba.z, 0.f);
    float r3 = fmaxf(acc[3] + c * s1.y + ba.w, 0.f);
    float r4 = fmaxf(acc[4] + c * s2.x + bb.x, 0.f);
    float r5 = fmaxf(acc[5] + c * s2.y + bb.y, 0.f);
    float r6 = fmaxf(acc[6] + c * s3.x + bb.z, 0.f);
    float r7 = fmaxf(acc[7] + c * s3.y + bb.w, 0.f);
    uint4 o;
    o.x = pack_h2(r0, r1);
    o.y = pack_h2(r2, r3);
    o.z = pack_h2(r4, r5);
    o.w = pack_h2(r6, r7);
    reinterpret_cast<uint4*>(out)[(size_t)node * 16 + sub] = o;
}

// ---------------- launcher --------------------------------------------------
extern "C" void kernel_launch(void* const* d_in, const int* in_sizes, int n_in,
                              void* d_out, int out_size)
{
    (void)in_sizes; (void)n_in; (void)out_size;
    const float* x  = (const float*)d_in[0];
    const int*   ei = (const int*)d_in[1];          // int32 (JAX x64 disabled)
    const float* W1 = (const float*)d_in[2];
    const float* b1 = (const float*)d_in[3];
    const float* W2 = (const float*)d_in[4];
    const float* b2 = (const float*)d_in[5];
    const float* Wl = (const float*)d_in[6];
    const float* bl = (const float*)d_in[7];
    float* out = (float*)d_out;

    void *pxh, *pbh, *pba, *pdeg, *pst;
    cudaGetSymbolAddress(&pxh, g_xh);
    cudaGetSymbolAddress(&pbh, g_bufh);
    cudaGetSymbolAddress(&pba, g_bufact);
    cudaGetSymbolAddress(&pdeg, g_deg);
    cudaGetSymbolAddress(&pst,  g_status);
    __half* xh = (__half*)pxh;
    __half* bufh = (__half*)pbh;
    __half* bufact = (__half*)pba;

    const int SMEM128 = (2 * 128 * 68 + 128 * 68) * 4;   // 104448 B
    const int SMEM64  = (2 * 128 * 68 + 64 * 68) * 4;    // 87040 B
    cudaFuncSetAttribute((const void*)k_gemm<128, true>,
                         cudaFuncAttributeMaxDynamicSharedMemorySize, SMEM128);
    cudaFuncSetAttribute((const void*)k_gemm<64, false>,
                         cudaFuncAttributeMaxDynamicSharedMemorySize, SMEM64);

    const int TB = 256;
    const int GB_E = (NE + TB - 1) / TB;           // 6250
    const int GB_C = (NN * 32 + TB - 1) / TB;      // 12500
    const int GB_A = (NN + 15) / 16;               // 6250 (16 nodes per block)

    // --- zero-init via memset nodes ---
    cudaMemsetAsync(pdeg, 0, NN * sizeof(int));
    cudaMemsetAsync(pst,  0, NB_SCAN * sizeof(int));

    // --- graph preprocessing ---
    k_count_cvt<<<GB_C, TB>>>(ei, (const float4*)x, (uint2*)xh);
    k_scan<<<NB_SCAN, 1024>>>();
    k_fill<<<GB_E, TB>>>(ei);

    // --- layer 1 ---
    k_gemm<128, true><<<GEMM_GRID, TB, SMEM128>>>(xh, W1, nullptr, bufh);
    k_agg_relu<<<GB_A, TB>>>(bufh, b1, bufact);

    // --- layer 2 ---
    k_gemm<128, true><<<GEMM_GRID, TB, SMEM128>>>(bufact, W2, nullptr, bufh);
    k_agg_relu<<<GB_A, TB>>>(bufh, b2, bufact);

    // --- readout ---
    k_gemm<64, false><<<GEMM_GRID, TB, SMEM64>>>(bufact, Wl, bl, out);
}

// round 17
// speedup vs baseline: 1.3053x; 1.0764x over previous
#include <cuda_runtime.h>
#include <cuda_fp16.h>
#include <cstdint>

// Problem constants (fixed by the dataset)
#define NN   100000       // nodes
#define NE   1600000      // edges (excluding self loops)
#define FD   128          // feature / hidden dim
#define NC   64           // classes
#define NB_SCAN 98        // ceil(NN / 1024)
#define NTILES 782        // ceil(NN / 128)
#define GEMM_GRID 296     // 2 CTAs/SM * 148 SMs

// ---------------- scratch (device globals; no allocation allowed) ----------
// g_bufh has ONE extra row (index NN) kept all-zero: padding target for the
// tail-free gather (pad src = NN contributes exactly 0).
__device__ __half g_xh[NN * FD];        // x converted to fp16 (GEMM-1 input)
__device__ __half g_bufh[(NN + 1) * FD];// GEMM output h' = dinv*h (gather src)
__device__ __half g_bufact[NN * FD];    // agg+relu output (fp16, GEMM input)
__device__ float  g_dinv[NN];
__device__ int    g_deg[NN];            // in-degree (without self loop)
__device__ int    g_rowstart[NN];       // AFTER k_fill: END offset of each row
__device__ int    g_src[NE];            // src per edge, grouped by dst
__device__ int    g_status[NB_SCAN];    // lookback scan status (memset to 0)

__device__ __forceinline__ uint32_t pack_h2(float x, float y)
{
    __half2 h = __floats2half2_rn(x, y);
    return *reinterpret_cast<uint32_t*>(&h);
}

// ---------------- preprocessing kernels ------------------------------------

// Fused: degree count (threads < NE) + x -> fp16 conversion (all 3.2M threads).
__global__ void k_count_cvt(const int* __restrict__ ei,
                            const float4* __restrict__ x,
                            uint2* __restrict__ xh)
{
    int i = blockIdx.x * blockDim.x + threadIdx.x;
    if (i < NE) {
        int d = ei[NE + i];
        atomicAdd(&g_deg[d], 1);
    }
    float4 v = __ldg(&x[i]);
    uint2 p;
    p.x = pack_h2(v.x, v.y);
    p.y = pack_h2(v.z, v.w);
    xh[i] = p;
}

// Single-pass scan over g_deg -> g_rowstart (exclusive), plus dinv.
__global__ void __launch_bounds__(1024) k_scan()
{
    __shared__ int s[1024];
    __shared__ int sh_prefix;
    int t = threadIdx.x;
    int i = blockIdx.x * 1024 + t;
    int v = (i < NN) ? g_deg[i] : 0;
    s[t] = v;
    __syncthreads();
    #pragma unroll
    for (int off = 1; off < 1024; off <<= 1) {
        int add = (t >= off) ? s[t - off] : 0;
        __syncthreads();
        s[t] += add;
        __syncthreads();
    }
    if (t == 1023) {
        int total = s[t];
        __threadfence();
        atomicExch(&g_status[blockIdx.x], total | 0x40000000);
    }
    if (t == 0) {
        int p = 0;
        for (int j = 0; j < (int)blockIdx.x; j++) {
            int st;
            do { st = atomicAdd(&g_status[j], 0); } while (!(st & 0x40000000));
            p += st & 0x3FFFFFFF;
        }
        sh_prefix = p;
    }
    __syncthreads();
    if (i < NN) {
        g_rowstart[i] = s[t] - v + sh_prefix;
        g_dinv[i] = rsqrtf((float)v + 1.0f);    // +1 = self loop
    }
}

// Bumps g_rowstart in place: after this kernel rowstart[d] == END of row d.
// Consumers compute beg = rowstart[d] - deg[d]. No norm computation here:
// dinv is folded into h' at the GEMM epilogue instead.
__global__ void k_fill(const int* __restrict__ ei)
{
    int e = blockIdx.x * blockDim.x + threadIdx.x;
    if (e < NE) {
        int s = ei[e];
        int d = ei[NE + e];
        int p = atomicAdd(&g_rowstart[d], 1);
        g_src[p] = s;
    }
}

// ---------------- fp16 MMA helper ------------------------------------------
__device__ __forceinline__ void mma_f16(
    float& d0, float& d1, float& d2, float& d3,
    uint32_t a0, uint32_t a1, uint32_t a2, uint32_t a3,
    uint32_t b0, uint32_t b1)
{
    asm volatile(
        "mma.sync.aligned.m16n8k16.row.col.f32.f16.f16.f32 "
        "{%0,%1,%2,%3}, {%4,%5,%6,%7}, {%8,%9}, {%0,%1,%2,%3};"
        : "+f"(d0), "+f"(d1), "+f"(d2), "+f"(d3)
        : "r"(a0), "r"(a1), "r"(a2), "r"(a3), "r"(b0), "r"(b1));
}

// ---------------- GEMM: C[NN, OUT] = A[NN,128] @ W[OUT,128]^T (+bias) ------
// Persistent multi-tile fp16 MMA GEMM with cp.async double-buffered A tiles.
// HOUT path writes h' = dinv[row] * gemm_out as fp16 (prefolded norm).
template <int OUT, bool HOUT>
__global__ void __launch_bounds__(256, 2) k_gemm(
    const __half* __restrict__ A, const float* __restrict__ W,
    const float* __restrict__ bias, void* __restrict__ Cv)
{
    constexpr int NA = OUT / 16;
    constexpr int XWORDS = 128 * 68;
    extern __shared__ uint32_t sm[];
    uint32_t* Xstage[2] = { sm, sm + XWORDS };
    uint32_t* Ws = sm + 2 * XWORDS;
    const int tid  = threadIdx.x;
    const int warp = tid >> 5;
    const int lane = tid & 31;

    const int m_off = (warp >> 1) * 32;
    const int n_off = (warp & 1) * (OUT / 2);
    const int gid = lane >> 2;
    const int tig = lane & 3;

    auto fill_async = [&](uint32_t* Xs, int t) {
        int row0 = t * 128;
        #pragma unroll
        for (int i = 0; i < 8; i++) {
            int idx = tid + i * 256;
            int r = idx >> 4, c8 = idx & 15;
            uint32_t dst = (uint32_t)__cvta_generic_to_shared(&Xs[r * 68 + c8 * 4]);
            const void* src = (const char*)A + ((size_t)(row0 + r) * 128 + c8 * 8) * 2;
            int sz = (row0 + r < NN) ? 16 : 0;
            asm volatile("cp.async.cg.shared.global [%0], [%1], 16, %2;"
                         :: "r"(dst), "l"(src), "r"(sz));
        }
        asm volatile("cp.async.commit_group;");
    };

    int tile = blockIdx.x;
    if (tile < NTILES) fill_async(Xstage[0], tile);

    for (int idx = tid; idx < OUT * 32; idx += 256) {
        int j = idx >> 5, c4 = idx & 31;
        float4 v = reinterpret_cast<const float4*>(W)[idx];
        uint2 p;
        p.x = pack_h2(v.x, v.y);
        p.y = pack_h2(v.z, v.w);
        *reinterpret_cast<uint2*>(&Ws[j * 68 + c4 * 2]) = p;
    }

    int stage = 0;
    for (; tile < NTILES; tile += GEMM_GRID) {
        int next = tile + GEMM_GRID;
        if (next < NTILES) {
            fill_async(Xstage[stage ^ 1], next);
            asm volatile("cp.async.wait_group 1;");
        } else {
            asm volatile("cp.async.wait_group 0;");
        }
        __syncthreads();
        const uint32_t* Xs = Xstage[stage];
        const int row0 = tile * 128;

        float acc[2][NA][4];
        #pragma unroll
        for (int ma = 0; ma < 2; ma++)
            #pragma unroll
            for (int na = 0; na < NA; na++)
                #pragma unroll
                for (int c = 0; c < 4; c++) acc[ma][na][c] = 0.f;

        #pragma unroll
        for (int ks = 0; ks < 8; ks++) {
            uint32_t a[2][4];
            #pragma unroll
            for (int ma = 0; ma < 2; ma++) {
                int row = m_off + ma * 16 + gid;
                a[ma][0] = Xs[row * 68 + ks * 8 + tig];
                a[ma][1] = Xs[(row + 8) * 68 + ks * 8 + tig];
                a[ma][2] = Xs[row * 68 + ks * 8 + tig + 4];
                a[ma][3] = Xs[(row + 8) * 68 + ks * 8 + tig + 4];
            }
            #pragma unroll
            for (int na = 0; na < NA; na++) {
                int n = n_off + na * 8 + gid;
                uint32_t b0 = Ws[n * 68 + ks * 8 + tig];
                uint32_t b1 = Ws[n * 68 + ks * 8 + tig + 4];
                #pragma unroll
                for (int ma = 0; ma < 2; ma++) {
                    float* d = acc[ma][na];
                    mma_f16(d[0], d[1], d[2], d[3],
                            a[ma][0], a[ma][1], a[ma][2], a[ma][3], b0, b1);
                }
            }
        }

        #pragma unroll
        for (int ma = 0; ma < 2; ma++) {
            #pragma unroll
            for (int na = 0; na < NA; na++) {
                int col = n_off + na * 8 + 2 * tig;
                float bx = 0.f, by = 0.f;
                if (bias) { bx = __ldg(&bias[col]); by = __ldg(&bias[col + 1]); }
                int r0 = row0 + m_off + ma * 16 + gid;
                int r1 = r0 + 8;
                if (HOUT) {
                    __half* C = (__half*)Cv;
                    if (r0 < NN) {
                        float dv = __ldg(&g_dinv[r0]);
                        *reinterpret_cast<__half2*>(&C[(size_t)r0 * OUT + col]) =
                            __floats2half2_rn(dv * acc[ma][na][0], dv * acc[ma][na][1]);
                    }
                    if (r1 < NN) {
                        float dv = __ldg(&g_dinv[r1]);
                        *reinterpret_cast<__half2*>(&C[(size_t)r1 * OUT + col]) =
                            __floats2half2_rn(dv * acc[ma][na][2], dv * acc[ma][na][3]);
                    }
                } else {
                    float* C = (float*)Cv;
                    if (r0 < NN)
                        *reinterpret_cast<float2*>(&C[(size_t)r0 * OUT + col]) =
                            make_float2(acc[ma][na][0] + bx, acc[ma][na][1] + by);
                    if (r1 < NN)
                        *reinterpret_cast<float2*>(&C[(size_t)r1 * OUT + col]) =
                            make_float2(acc[ma][na][2] + bx, acc[ma][na][3] + by);
                }
            }
        }
        __syncthreads();
        stage ^= 1;
    }
}

// -------- aggregation + self-loop + bias + ReLU: HALF-WARP per node --------
// h' = dinv*h prefolded: inner loop is PURE fp16 adds of gathered rows.
// 8 edges accumulated in 4 half2 regs (HADD2), spilled to fp32 per group.
// Pad src = NN -> all-zero row (g_bufh row NN), keeping the loop tail-free.
// result = dinv_d * (sum + h'[self]) + bias, relu, fp16 out.
__global__ void __launch_bounds__(256, 4) k_agg_relu(
    const __half* __restrict__ h,
    const float* __restrict__ bias,
    __half* __restrict__ out)
{
    const int lane = threadIdx.x & 31;
    const int halfid = lane >> 4;
    const int sub  = lane & 15;
    int node = ((blockIdx.x * blockDim.x + threadIdx.x) >> 5) * 2 + halfid;
    if (node >= NN) return;
    const unsigned mask = 0xFFFFu << (halfid * 16);

    const int end = g_rowstart[node];
    const int cnt = g_deg[node];
    const int beg = end - cnt;
    const uint4* hp = reinterpret_cast<const uint4*>(h);     // 16 uint4 / row

    float acc[8];
    #pragma unroll
    for (int d = 0; d < 8; d++) acc[d] = 0.f;

    for (int t0 = 0; t0 < cnt; t0 += 16) {
        int sreg = NN;                              // pad -> zero row
        if (t0 + sub < cnt) sreg = __ldg(&g_src[beg + t0 + sub]);
        int m = cnt - t0;
        #pragma unroll
        for (int g = 0; g < 2; g++) {
            if (g * 8 >= m) break;
            uint4 u[8];
            #pragma unroll
            for (int q = 0; q < 8; q++) {
                int src = __shfl_sync(mask, sreg, (halfid << 4) + g * 8 + q);
                u[q] = __ldg(&hp[(size_t)src * 16 + sub]);
            }
            __half2 h0 = __float2half2_rn(0.f);
            __half2 h1 = h0, h2 = h0, h3 = h0;
            #pragma unroll
            for (int q = 0; q < 8; q++) {
                h0 = __hadd2(h0, *reinterpret_cast<__half2*>(&u[q].x));
                h1 = __hadd2(h1, *reinterpret_cast<__half2*>(&u[q].y));
                h2 = __hadd2(h2, *reinterpret_cast<__half2*>(&u[q].z));
                h3 = __hadd2(h3, *reinterpret_cast<__half2*>(&u[q].w));
            }
            float2 p0 = __half22float2(h0);
            float2 p1 = __half22float2(h1);
            float2 p2 = __half22float2(h2);
            float2 p3 = __half22float2(h3);
            acc[0] += p0.x; acc[1] += p0.y;
            acc[2] += p1.x; acc[3] += p1.y;
            acc[4] += p2.x; acc[5] += p2.y;
            acc[6] += p3.x; acc[7] += p3.y;
        }
    }

    // self-loop: + h'[self]; then scale by dinv_d, add bias, relu
    float dinv_d = g_dinv[node];
    uint4 us = __ldg(&hp[(size_t)node * 16 + sub]);
    float2 s0 = __half22float2(*reinterpret_cast<__half2*>(&us.x));
    float2 s1 = __half22float2(*reinterpret_cast<__half2*>(&us.y));
    float2 s2 = __half22float2(*reinterpret_cast<__half2*>(&us.z));
    float2 s3 = __half22float2(*reinterpret_cast<__half2*>(&us.w));
    const float4* b4 = reinterpret_cast<const float4*>(bias);
    float4 ba = __ldg(&b4[sub * 2]);
    float4 bb = __ldg(&b4[sub * 2 + 1]);
    float r0 = fmaxf(dinv_d * (acc[0] + s0.x) + ba.x, 0.f);
    float r1 = fmaxf(dinv_d * (acc[1] + s0.y) + ba.y, 0.f);
    float r2 = fmaxf(dinv_d * (acc[2] + s1.x) + ba.z, 0.f);
    float r3 = fmaxf(dinv_d * (acc[3] + s1.y) + ba.w, 0.f);
    float r4 = fmaxf(dinv_d * (acc[4] + s2.x) + bb.x, 0.f);
    float r5 = fmaxf(dinv_d * (acc[5] + s2.y) + bb.y, 0.f);
    float r6 = fmaxf(dinv_d * (acc[6] + s3.x) + bb.z, 0.f);
    float r7 = fmaxf(dinv_d * (acc[7] + s3.y) + bb.w, 0.f);
    uint4 o;
    o.x = pack_h2(r0, r1);
    o.y = pack_h2(r2, r3);
    o.z = pack_h2(r4, r5);
    o.w = pack_h2(r6, r7);
    reinterpret_cast<uint4*>(out)[(size_t)node * 16 + sub] = o;
}

// ---------------- launcher --------------------------------------------------
extern "C" void kernel_launch(void* const* d_in, const int* in_sizes, int n_in,
                              void* d_out, int out_size)
{
    (void)in_sizes; (void)n_in; (void)out_size;
    const float* x  = (const float*)d_in[0];
    const int*   ei = (const int*)d_in[1];          // int32 (JAX x64 disabled)
    const float* W1 = (const float*)d_in[2];
    const float* b1 = (const float*)d_in[3];
    const float* W2 = (const float*)d_in[4];
    const float* b2 = (const float*)d_in[5];
    const float* Wl = (const float*)d_in[6];
    const float* bl = (const float*)d_in[7];
    float* out = (float*)d_out;

    void *pxh, *pbh, *pba, *pdeg, *pst;
    cudaGetSymbolAddress(&pxh, g_xh);
    cudaGetSymbolAddress(&pbh, g_bufh);
    cudaGetSymbolAddress(&pba, g_bufact);
    cudaGetSymbolAddress(&pdeg, g_deg);
    cudaGetSymbolAddress(&pst,  g_status);
    __half* xh = (__half*)pxh;
    __half* bufh = (__half*)pbh;
    __half* bufact = (__half*)pba;

    const int SMEM128 = (2 * 128 * 68 + 128 * 68) * 4;   // 104448 B
    const int SMEM64  = (2 * 128 * 68 + 64 * 68) * 4;    // 87040 B
    cudaFuncSetAttribute((const void*)k_gemm<128, true>,
                         cudaFuncAttributeMaxDynamicSharedMemorySize, SMEM128);
    cudaFuncSetAttribute((const void*)k_gemm<64, false>,
                         cudaFuncAttributeMaxDynamicSharedMemorySize, SMEM64);

    const int TB = 256;
    const int GB_E = (NE + TB - 1) / TB;           // 6250
    const int GB_C = (NN * 32 + TB - 1) / TB;      // 12500
    const int GB_A = (NN + 15) / 16;               // 6250 (16 nodes per block)

    // --- zero-init via memset nodes ---
    cudaMemsetAsync(pdeg, 0, NN * sizeof(int));
    cudaMemsetAsync(pst,  0, NB_SCAN * sizeof(int));
    // zero pad row NN of g_bufh (gather target for padded edges)
    cudaMemsetAsync((char*)pbh + (size_t)NN * FD * sizeof(__half), 0,
                    FD * sizeof(__half));

    // --- graph preprocessing ---
    k_count_cvt<<<GB_C, TB>>>(ei, (const float4*)x, (uint2*)xh);
    k_scan<<<NB_SCAN, 1024>>>();
    k_fill<<<GB_E, TB>>>(ei);

    // --- layer 1 ---
    k_gemm<128, true><<<GEMM_GRID, TB, SMEM128>>>(xh, W1, nullptr, bufh);
    k_agg_relu<<<GB_A, TB>>>(bufh, b1, bufact);

    // --- layer 2 ---
    k_gemm<128, true><<<GEMM_GRID, TB, SMEM128>>>(bufact, W2, nullptr, bufh);
    k_agg_relu<<<GB_A, TB>>>(bufh, b2, bufact);

    // --- readout ---
    k_gemm<64, false><<<GEMM_GRID, TB, SMEM64>>>(bufact, Wl, bl, out);
}